// round 15
// baseline (speedup 1.0000x reference)
#include <cuda_runtime.h>
#include <cuda_fp16.h>
#include <math.h>
#include <stdint.h>

#define BB   16
#define CIN  512
#define TT   4096
#define EE   64
#define KK   2048
#define NPTS (BB * TT)        // 65536
#define ZLEN (NPTS * EE)      // 4194304

// fp16 split of a float2: v = hi + lo elementwise, packed as half2 (u32 bits)
__device__ __forceinline__ void f16s(float2 v, uint32_t& hi, uint32_t& lo) {
    __half2 h = __floats2half2_rn(v.x, v.y);
    float2 hf = __half22float2(h);
    __half2 l = __floats2half2_rn(v.x - hf.x, v.y - hf.y);
    hi = *(uint32_t*)&h;
    lo = *(uint32_t*)&l;
}

// m16n8k16 fp16 MMA, fp32 accumulate
#define MMAF16(c0, c1, c2, c3, a0, a1, a2, a3, b0, b1)                        \
    asm("mma.sync.aligned.m16n8k16.row.col.f32.f16.f16.f32 "                  \
        "{%0,%1,%2,%3}, {%4,%5,%6,%7}, {%8,%9}, {%0,%1,%2,%3};"               \
        : "+f"(c0), "+f"(c1), "+f"(c2), "+f"(c3)                              \
        : "r"(a0), "r"(a1), "r"(a2), "r"(a3), "r"(b0), "r"(b1))

// m16n8k16 fp16 MMA, fp16 accumulate (C/D = 2 x f16x2 regs)
#define MMAF16A(cc0, cc1, a0, a1, a2, a3, b0, b1)                             \
    asm("mma.sync.aligned.m16n8k16.row.col.f16.f16.f16.f16 "                  \
        "{%0,%1}, {%2,%3,%4,%5}, {%6,%7}, {%0,%1};"                           \
        : "+r"(cc0), "+r"(cc1)                                                \
        : "r"(a0), "r"(a1), "r"(a2), "r"(a3), "r"(b0), "r"(b1))

// packed-fragment slot (bytes within a 160B row) for k-pair index l (k=2l)
__device__ __forceinline__ uint32_t fslot(int l) {
    return (uint32_t)((((l >> 3) * 4 + (l & 3)) << 3) + (((l >> 2) & 1) << 2));
}

__device__ __forceinline__ uint32_t smem_u32(const void* p) {
    uint32_t a;
    asm("{ .reg .u64 t; cvta.to.shared.u64 t, %1; cvt.u32.u64 %0, t; }"
        : "=r"(a) : "l"(p));
    return a;
}
__device__ __forceinline__ void cpa16(uint32_t saddr, const void* g) {
    asm volatile("cp.async.cg.shared.global [%0], [%1], 16;"
                 :: "r"(saddr), "l"(g) : "memory");
}
#define CPA_COMMIT() asm volatile("cp.async.commit_group;" ::: "memory")
#define CPA_WAIT0()  asm volatile("cp.async.wait_group 0;" ::: "memory")

// ---------------- device scratch ----------------
__device__ __align__(16) float g_enorm[KK];      // ||e_k||^2
__device__ int      g_counts[KK];                // histogram
__device__ float    g_partials[256];             // per-CTA commitment partials
__device__ __align__(16) uint32_t g_wfh[8 * 64 * 40];   // w fragments hi
__device__ __align__(16) uint32_t g_wfl[8 * 64 * 40];   // w fragments lo
__device__ __align__(16) uint32_t g_ebh[KK * 40];        // codebook frags hi
__device__ __align__(16) uint32_t g_ebl[KK * 40];        // codebook frags lo

// ---------------- prep: norms + counts + both fragment pre-splits ----------
__global__ void k_prep(const float* __restrict__ embed,
                       const float* __restrict__ w) {
    int i = blockIdx.x * 256 + threadIdx.x;      // 0..65535

    {   // codebook fragment split (KK*32 = 65536 items)
        int k = i >> 5;
        int l = i & 31;
        float2 v = *(const float2*)(embed + (size_t)k * EE + 2 * l);
        uint32_t hi, lo;
        f16s(v, hi, lo);
        uint32_t off = (uint32_t)(k * 40) + (fslot(l) >> 2);
        g_ebh[off] = hi;
        g_ebl[off] = lo;
    }
    if (i < 8 * 64 * 32) {    // w fragment split
        int ch = i >> 11;
        int e  = (i >> 5) & 63;
        int l  = i & 31;
        float2 v = *(const float2*)(w + (size_t)e * CIN + ch * 64 + 2 * l);
        uint32_t hi, lo;
        f16s(v, hi, lo);
        uint32_t off = (uint32_t)(ch * 64 * 40 + e * 40) + (fslot(l) >> 2);
        g_wfh[off] = hi;
        g_wfl[off] = lo;
    }
    if (i < KK) {             // norms + zero counts
        const float4* row = (const float4*)(embed + (size_t)i * EE);
        float s = 0.f;
#pragma unroll
        for (int j = 0; j < 16; ++j) {
            float4 v = row[j];
            s += v.x * v.x + v.y * v.y + v.z * v.z + v.w * v.w;
        }
        g_enorm[i] = s;
        g_counts[i] = 0;
    }
}

// ---------------- fused projection + distance argmin + outputs ------------
#define PX0   0
#define PX1   33280
#define PWH0  66560
#define PWH1  72704
#define PWL0  78848
#define PWL1  84992
#define PTOT  91136
// dist-phase overlay offsets (reused region, after syncthreads)
#define DBH   0
#define DBL   20480
#define DSN   40960
#define DRED  41472
#define DSQ   33280

__global__ __launch_bounds__(256, 2) void k_fused(const float* __restrict__ x,
                                                  const float* __restrict__ pb,
                                                  const float* __restrict__ embed,
                                                  float* __restrict__ out) {
    extern __shared__ char sm[];
    uint32_t sbase = smem_u32(sm);

    int tid  = threadIdx.x;
    int wid  = tid >> 5;
    int lane = tid & 31;
    int g = lane >> 2;
    int q = lane & 3;

    int b  = blockIdx.x >> 4;
    int t0 = (blockIdx.x & 15) * 256;
    const float* xb = x + (size_t)b * CIN * TT + t0;
    int m0 = wid * 32 + g;

    // ================= Phase 1: projection =================
    float acc[2][8][4];
#pragma unroll
    for (int ti = 0; ti < 2; ++ti)
#pragma unroll
        for (int nb = 0; nb < 8; ++nb)
#pragma unroll
            for (int j = 0; j < 4; ++j) acc[ti][nb][j] = 0.f;

    auto stage_p = [&](int cc, int buf) {
        uint32_t xa = sbase + (buf ? PX1 : PX0);
#pragma unroll
        for (int p = 0; p < 8; ++p) {
            int idx = tid + p * 256;
            int c = idx >> 6;
            int f = idx & 63;
            cpa16(xa + (uint32_t)(c * 260 + f * 4) * 4,
                  xb + (size_t)(cc * 32 + c) * TT + f * 4);
        }
        int ch = cc >> 1;
        int hf = cc & 1;
        const uint4* wh = (const uint4*)(g_wfh + ch * 2560 + hf * 16);
        const uint4* wl = (const uint4*)(g_wfl + ch * 2560 + hf * 16);
        uint32_t ha = sbase + (buf ? PWH1 : PWH0);
        uint32_t la = sbase + (buf ? PWL1 : PWL0);
        {
            int e = tid >> 2;
            int part = tid & 3;
            cpa16(ha + (uint32_t)(e * 96 + part * 16), wh + e * 10 + part);
            cpa16(la + (uint32_t)(e * 96 + part * 16), wl + e * 10 + part);
        }
        CPA_COMMIT();
    };

    stage_p(0, 0);

    for (int cc = 0; cc < 16; ++cc) {
        CPA_WAIT0();
        __syncthreads();
        if (cc + 1 < 16) stage_p(cc + 1, (cc + 1) & 1);

        const float* xs = (const float*)(sm + ((cc & 1) ? PX1 : PX0));
        const unsigned char* sWh = (const unsigned char*)(sm + ((cc & 1) ? PWH1 : PWH0));
        const unsigned char* sWl = (const unsigned char*)(sm + ((cc & 1) ? PWL1 : PWL0));

#pragma unroll
        for (int s = 0; s < 2; ++s) {
            int c = s * 16 + 2 * q;
            uint32_t Xh[2][4], Xl[2][4];
#pragma unroll
            for (int ti = 0; ti < 2; ++ti) {
                int m = m0 + ti * 16;
                f16s(make_float2(xs[c * 260 + m],           xs[(c + 1) * 260 + m]),     Xh[ti][0], Xl[ti][0]);
                f16s(make_float2(xs[c * 260 + m + 8],       xs[(c + 1) * 260 + m + 8]), Xh[ti][1], Xl[ti][1]);
                f16s(make_float2(xs[(c + 8) * 260 + m],     xs[(c + 9) * 260 + m]),     Xh[ti][2], Xl[ti][2]);
                f16s(make_float2(xs[(c + 8) * 260 + m + 8], xs[(c + 9) * 260 + m + 8]), Xh[ti][3], Xl[ti][3]);
            }
#pragma unroll
            for (int nb = 0; nb < 8; ++nb) {
                uint32_t boff = (uint32_t)((nb * 8 + g) * 96 + q * 8 + s * 32);
                uint2 bh = *(const uint2*)(sWh + boff);
                uint2 bl = *(const uint2*)(sWl + boff);
#pragma unroll
                for (int ti = 0; ti < 2; ++ti) {
                    MMAF16(acc[ti][nb][0], acc[ti][nb][1], acc[ti][nb][2], acc[ti][nb][3],
                           Xh[ti][0], Xh[ti][1], Xh[ti][2], Xh[ti][3], bh.x, bh.y);
                    MMAF16(acc[ti][nb][0], acc[ti][nb][1], acc[ti][nb][2], acc[ti][nb][3],
                           Xh[ti][0], Xh[ti][1], Xh[ti][2], Xh[ti][3], bl.x, bl.y);
                    MMAF16(acc[ti][nb][0], acc[ti][nb][1], acc[ti][nb][2], acc[ti][nb][3],
                           Xl[ti][0], Xl[ti][1], Xl[ti][2], Xl[ti][3], bh.x, bh.y);
                }
            }
        }
    }

    // ---- bias + ||h||^2 + split accumulators directly into dist A frags ----
    uint32_t A0h[4][4], A0l[4][4], A1h[4][4], A1l[4][4];
    float hn0 = 0.f, hn1 = 0.f, hn2 = 0.f, hn3 = 0.f;
#pragma unroll
    for (int nb = 0; nb < 8; ++nb) {
        float2 bv = *(const float2*)(pb + nb * 8 + 2 * q);
        int s = nb >> 1;
        int odd = nb & 1;
        {   // ti = 0 (rows m0, m0+8)
            float v0 = acc[0][nb][0] + bv.x;
            float v1 = acc[0][nb][1] + bv.y;
            float v2 = acc[0][nb][2] + bv.x;
            float v3 = acc[0][nb][3] + bv.y;
            hn0 += v0 * v0 + v1 * v1;
            hn1 += v2 * v2 + v3 * v3;
            f16s(make_float2(v0, v1), A0h[s][odd ? 2 : 0], A0l[s][odd ? 2 : 0]);
            f16s(make_float2(v2, v3), A0h[s][odd ? 3 : 1], A0l[s][odd ? 3 : 1]);
        }
        {   // ti = 1 (rows m0+16, m0+24)
            float v0 = acc[1][nb][0] + bv.x;
            float v1 = acc[1][nb][1] + bv.y;
            float v2 = acc[1][nb][2] + bv.x;
            float v3 = acc[1][nb][3] + bv.y;
            hn2 += v0 * v0 + v1 * v1;
            hn3 += v2 * v2 + v3 * v3;
            f16s(make_float2(v0, v1), A1h[s][odd ? 2 : 0], A1l[s][odd ? 2 : 0]);
            f16s(make_float2(v2, v3), A1h[s][odd ? 3 : 1], A1l[s][odd ? 3 : 1]);
        }
    }

    __syncthreads();   // projection smem fully dead before dist overlay

    // ================= Phase 2: distance argmin =================
    uint32_t a_sbh = sbase + DBH;
    uint32_t a_sbl = sbase + DBL;
    uint32_t a_sn  = sbase + DSN;
    float* red = (float*)(sm + DRED);

    auto stage = [&](int c, int buf) {
        const uint4* gh = ((const uint4*)g_ebh) + c * 640;
        const uint4* gl = ((const uint4*)g_ebl) + c * 640;
#pragma unroll
        for (int p = 0; p < 3; ++p) {
            int i = tid + p * 256;
            if (i < 640) {
                cpa16(a_sbh + buf * 10240 + i * 16, gh + i);
                cpa16(a_sbl + buf * 10240 + i * 16, gl + i);
            }
        }
        if (tid < 16)
            cpa16(a_sn + buf * 256 + tid * 16,
                  ((const uint4*)(g_enorm + c * 64)) + tid);
        CPA_COMMIT();
    };

    float bA0 = 3.4e38f, bB0 = 3.4e38f, bA1 = 3.4e38f, bB1 = 3.4e38f;
    int   kA0 = 0, kB0 = 0, kA1 = 0, kB1 = 0;

    stage(0, 0);

    for (int c = 0; c < 32; ++c) {
        CPA_WAIT0();
        __syncthreads();
        if (c + 1 < 32) stage(c + 1, (c + 1) & 1);

        const unsigned char* bufh = (const unsigned char*)(sm + DBH + (c & 1) * 10240);
        const unsigned char* bufl = (const unsigned char*)(sm + DBL + (c & 1) * 10240);
        const float* sn = (const float*)(sm + DSN + (c & 1) * 256);

#pragma unroll
        for (int nb = 0; nb < 8; ++nb) {
            // main terms: fp32 accumulate; cross terms: fp16 accumulate
            float c0 = 0.f, c1 = 0.f, c2 = 0.f, c3 = 0.f;   // tile0 main
            float d0 = 0.f, d1 = 0.f, d2 = 0.f, d3 = 0.f;   // tile1 main
            uint32_t x0 = 0u, x1 = 0u;                       // tile0 cross f16x2
            uint32_t y0 = 0u, y1 = 0u;                       // tile1 cross f16x2
            uint32_t bo = (uint32_t)((nb * 8 + g) * 160 + q * 8);
#pragma unroll
            for (int s = 0; s < 4; ++s) {
                uint2 bh = *(const uint2*)(bufh + bo + s * 32);
                uint2 bl = *(const uint2*)(bufl + bo + s * 32);
                MMAF16(c0, c1, c2, c3, A0h[s][0], A0h[s][1], A0h[s][2], A0h[s][3], bh.x, bh.y);
                MMAF16(d0, d1, d2, d3, A1h[s][0], A1h[s][1], A1h[s][2], A1h[s][3], bh.x, bh.y);
                MMAF16A(x0, x1, A0h[s][0], A0h[s][1], A0h[s][2], A0h[s][3], bl.x, bl.y);
                MMAF16A(y0, y1, A1h[s][0], A1h[s][1], A1h[s][2], A1h[s][3], bl.x, bl.y);
                MMAF16A(x0, x1, A0l[s][0], A0l[s][1], A0l[s][2], A0l[s][3], bh.x, bh.y);
                MMAF16A(y0, y1, A1l[s][0], A1l[s][1], A1l[s][2], A1l[s][3], bh.x, bh.y);
            }
            float2 xc0 = __half22float2(*(__half2*)&x0);   // (g,2q),(g,2q+1)
            float2 xc1 = __half22float2(*(__half2*)&x1);   // (g+8,2q),(g+8,2q+1)
            float2 yc0 = __half22float2(*(__half2*)&y0);
            float2 yc1 = __half22float2(*(__half2*)&y1);

            int kb = c * 64 + nb * 8;
            float sn0 = sn[nb * 8 + 2 * q];
            float sn1 = sn[nb * 8 + 2 * q + 1];
            float s0 = fmaf(-2.f, c0 + xc0.x, sn0);
            float s1 = fmaf(-2.f, c1 + xc0.y, sn1);
            float s2 = fmaf(-2.f, c2 + xc1.x, sn0);
            float s3 = fmaf(-2.f, c3 + xc1.y, sn1);
            float u0 = fmaf(-2.f, d0 + yc0.x, sn0);
            float u1 = fmaf(-2.f, d1 + yc0.y, sn1);
            float u2 = fmaf(-2.f, d2 + yc1.x, sn0);
            float u3 = fmaf(-2.f, d3 + yc1.y, sn1);
            if (s0 < bA0) { bA0 = s0; kA0 = kb + 2 * q; }
            if (s1 < bA0) { bA0 = s1; kA0 = kb + 2 * q + 1; }
            if (s2 < bB0) { bB0 = s2; kB0 = kb + 2 * q; }
            if (s3 < bB0) { bB0 = s3; kB0 = kb + 2 * q + 1; }
            if (u0 < bA1) { bA1 = u0; kA1 = kb + 2 * q; }
            if (u1 < bA1) { bA1 = u1; kA1 = kb + 2 * q + 1; }
            if (u2 < bB1) { bB1 = u2; kB1 = kb + 2 * q; }
            if (u3 < bB1) { bB1 = u3; kB1 = kb + 2 * q + 1; }
        }
    }

#pragma unroll
    for (int off = 1; off <= 2; off <<= 1) {
        float o; int k;
        o = __shfl_xor_sync(0xffffffffu, bA0, off);
        k = __shfl_xor_sync(0xffffffffu, kA0, off);
        if (o < bA0 || (o == bA0 && k < kA0)) { bA0 = o; kA0 = k; }
        o = __shfl_xor_sync(0xffffffffu, bB0, off);
        k = __shfl_xor_sync(0xffffffffu, kB0, off);
        if (o < bB0 || (o == bB0 && k < kB0)) { bB0 = o; kB0 = k; }
        o = __shfl_xor_sync(0xffffffffu, bA1, off);
        k = __shfl_xor_sync(0xffffffffu, kA1, off);
        if (o < bA1 || (o == bA1 && k < kA1)) { bA1 = o; kA1 = k; }
        o = __shfl_xor_sync(0xffffffffu, bB1, off);
        k = __shfl_xor_sync(0xffffffffu, kB1, off);
        if (o < bB1 || (o == bB1 && k < kB1)) { bB1 = o; kB1 = k; }
        hn0 += __shfl_xor_sync(0xffffffffu, hn0, off);
        hn1 += __shfl_xor_sync(0xffffffffu, hn1, off);
        hn2 += __shfl_xor_sync(0xffffffffu, hn2, off);
        hn3 += __shfl_xor_sync(0xffffffffu, hn3, off);
    }

    __syncthreads();   // all fragment-buffer reads complete before overlay

    int* sq = (int*)(sm + DSQ);     // 256 point indices
    if (q == 0) {
        sq[wid * 32 + g]      = kA0;
        sq[wid * 32 + 8 + g]  = kB0;
        sq[wid * 32 + 16 + g] = kA1;
        sq[wid * 32 + 24 + g] = kB1;
        atomicAdd(&g_counts[kA0], 1);
        atomicAdd(&g_counts[kB0], 1);
        atomicAdd(&g_counts[kA1], 1);
        atomicAdd(&g_counts[kB1], 1);
    }

    float contrib = (q == 0)
        ? (bA0 + hn0) + (bB0 + hn1) + (bA1 + hn2) + (bB1 + hn3) : 0.f;
#pragma unroll
    for (int off = 16; off > 0; off >>= 1)
        contrib += __shfl_xor_sync(0xffffffffu, contrib, off);
    if (lane == 0) red[wid] = contrib;
    __syncthreads();
    if (tid == 0) {
        float s = 0.f;
#pragma unroll
        for (int i = 0; i < 8; ++i) s += red[i];
        g_partials[blockIdx.x] = s;
    }

    // ---- gather + transpose + output, 2 passes of 128 t ----
    float* zq = (float*)sm;          // [128][65]
    for (int p = 0; p < 2; ++p) {
        __syncthreads();
        int tl = tid >> 1;
        int hf = tid & 1;
        int qi = sq[p * 128 + tl];
        const float4* ep = (const float4*)(embed + (size_t)qi * EE + hf * 32);
#pragma unroll
        for (int j = 0; j < 8; ++j) {
            float4 z = ep[j];
            int e = hf * 32 + j * 4;
            zq[tl * 65 + e + 0] = z.x;
            zq[tl * 65 + e + 1] = z.y;
            zq[tl * 65 + e + 2] = z.z;
            zq[tl * 65 + e + 3] = z.w;
        }
        __syncthreads();
#pragma unroll
        for (int i = 0; i < 32; ++i) {
            int idx = i * 256 + tid;
            int e  = idx >> 7;
            int tt = idx & 127;
            out[((size_t)(b * EE + e)) * TT + t0 + p * 128 + tt] =
                zq[tt * 65 + e];
        }
    }
}

// ---------------- finalize scalars: fully parallel, float ----------------
__global__ __launch_bounds__(1024) void k_fin(float* __restrict__ out,
                                              int out_size) {
    __shared__ float slp[32], scm[32];
    int tid = threadIdx.x;

    float lp = 0.f;
#pragma unroll
    for (int k = tid; k < KK; k += 1024) {
        float p = (float)g_counts[k] * (1.f / (float)NPTS);
        lp -= p * logf(p + 1e-10f);
    }
    float cm = (tid < 256) ? g_partials[tid] : 0.f;

#pragma unroll
    for (int o = 16; o > 0; o >>= 1) {
        lp += __shfl_xor_sync(0xffffffffu, lp, o);
        cm += __shfl_xor_sync(0xffffffffu, cm, o);
    }
    if ((tid & 31) == 0) { slp[tid >> 5] = lp; scm[tid >> 5] = cm; }
    __syncthreads();

    if (tid < 32) {
        lp = slp[tid];
        cm = scm[tid];
#pragma unroll
        for (int o = 16; o > 0; o >>= 1) {
            lp += __shfl_xor_sync(0xffffffffu, lp, o);
            cm += __shfl_xor_sync(0xffffffffu, cm, o);
        }
        if (tid == 0 && out_size >= ZLEN + 18) {
            out[ZLEN + 17] = lp;
            out[ZLEN] = 0.25f * cm / ((float)NPTS * (float)EE);
        }
    }
    if (out_size >= ZLEN + 18 && tid >= 64 && tid < 80)
        out[ZLEN + 1 + (tid - 64)] = (float)(log(2048.0) * 4096.0);
}

// ---------------- launch ----------------
extern "C" void kernel_launch(void* const* d_in, const int* in_sizes, int n_in,
                              void* d_out, int out_size) {
    const float* x  = (const float*)d_in[0];   // [B, CIN, T]
    const float* w  = (const float*)d_in[1];   // [E, CIN]
    const float* pb = (const float*)d_in[2];   // [E]
    const float* em = (const float*)d_in[3];   // [K, E]
    float* out = (float*)d_out;

    static int smem_set = 0;
    if (!smem_set) {
        cudaFuncSetAttribute(k_fused,
                             cudaFuncAttributeMaxDynamicSharedMemorySize, PTOT);
        smem_set = 1;
    }

    k_prep<<<256, 256>>>(em, w);
    k_fused<<<NPTS / 256, 256, PTOT>>>(x, pb, em, out);
    k_fin<<<1, 1024>>>(out, out_size);
}

// round 17
// speedup vs baseline: 1.0344x; 1.0344x over previous
#include <cuda_runtime.h>
#include <cuda_fp16.h>
#include <math.h>
#include <stdint.h>

#define BB   16
#define CIN  512
#define TT   4096
#define EE   64
#define KK   2048
#define NPTS (BB * TT)        // 65536
#define ZLEN (NPTS * EE)      // 4194304

// fp16 split of a float2: v = hi + lo elementwise, packed as half2 (u32 bits)
__device__ __forceinline__ void f16s(float2 v, uint32_t& hi, uint32_t& lo) {
    __half2 h = __floats2half2_rn(v.x, v.y);
    float2 hf = __half22float2(h);
    __half2 l = __floats2half2_rn(v.x - hf.x, v.y - hf.y);
    hi = *(uint32_t*)&h;
    lo = *(uint32_t*)&l;
}

// m16n8k16 fp16 MMA, fp32 accumulate
#define MMAF16(c0, c1, c2, c3, a0, a1, a2, a3, b0, b1)                        \
    asm("mma.sync.aligned.m16n8k16.row.col.f32.f16.f16.f32 "                  \
        "{%0,%1,%2,%3}, {%4,%5,%6,%7}, {%8,%9}, {%0,%1,%2,%3};"               \
        : "+f"(c0), "+f"(c1), "+f"(c2), "+f"(c3)                              \
        : "r"(a0), "r"(a1), "r"(a2), "r"(a3), "r"(b0), "r"(b1))

// packed-fragment slot (bytes within a 160B row) for k-pair index l (k=2l)
__device__ __forceinline__ uint32_t fslot(int l) {
    return (uint32_t)((((l >> 3) * 4 + (l & 3)) << 3) + (((l >> 2) & 1) << 2));
}

__device__ __forceinline__ uint32_t smem_u32(const void* p) {
    uint32_t a;
    asm("{ .reg .u64 t; cvta.to.shared.u64 t, %1; cvt.u32.u64 %0, t; }"
        : "=r"(a) : "l"(p));
    return a;
}
__device__ __forceinline__ void cpa16(uint32_t saddr, const void* g) {
    asm volatile("cp.async.cg.shared.global [%0], [%1], 16;"
                 :: "r"(saddr), "l"(g) : "memory");
}
#define CPA_COMMIT() asm volatile("cp.async.commit_group;" ::: "memory")
#define CPA_WAIT0()  asm volatile("cp.async.wait_group 0;" ::: "memory")

// ---------------- device scratch ----------------
__device__ __align__(16) float g_enorm[KK];      // ||e_k||^2
__device__ int      g_counts[KK];                // histogram
__device__ float    g_partials[256];             // per-CTA commitment partials
__device__ int      g_done;                      // last-block counter
__device__ __align__(16) uint32_t g_wfh[8 * 64 * 40];   // w fragments hi
__device__ __align__(16) uint32_t g_wfl[8 * 64 * 40];   // w fragments lo
__device__ __align__(16) uint32_t g_ebh[KK * 40];        // codebook frags hi
__device__ __align__(16) uint32_t g_ebl[KK * 40];        // codebook frags lo

// ---------------- prep: norms + counts + both fragment pre-splits ----------
__global__ void k_prep(const float* __restrict__ embed,
                       const float* __restrict__ w) {
    int i = blockIdx.x * 256 + threadIdx.x;      // 0..65535

    {   // codebook fragment split (KK*32 = 65536 items)
        int k = i >> 5;
        int l = i & 31;
        float2 v = *(const float2*)(embed + (size_t)k * EE + 2 * l);
        uint32_t hi, lo;
        f16s(v, hi, lo);
        uint32_t off = (uint32_t)(k * 40) + (fslot(l) >> 2);
        g_ebh[off] = hi;
        g_ebl[off] = lo;
    }
    if (i < 8 * 64 * 32) {    // w fragment split
        int ch = i >> 11;
        int e  = (i >> 5) & 63;
        int l  = i & 31;
        float2 v = *(const float2*)(w + (size_t)e * CIN + ch * 64 + 2 * l);
        uint32_t hi, lo;
        f16s(v, hi, lo);
        uint32_t off = (uint32_t)(ch * 64 * 40 + e * 40) + (fslot(l) >> 2);
        g_wfh[off] = hi;
        g_wfl[off] = lo;
    }
    if (i < KK) {             // norms + zero counts
        const float4* row = (const float4*)(embed + (size_t)i * EE);
        float s = 0.f;
#pragma unroll
        for (int j = 0; j < 16; ++j) {
            float4 v = row[j];
            s += v.x * v.x + v.y * v.y + v.z * v.z + v.w * v.w;
        }
        g_enorm[i] = s;
        g_counts[i] = 0;
    }
    if (i == 0) g_done = 0;
}

// ---------------- fused projection + distance argmin + outputs + finalize --
#define PX0   0
#define PX1   33280
#define PWH0  66560
#define PWH1  72704
#define PWL0  78848
#define PWL1  84992
#define PTOT  91136
// dist-phase overlay offsets (reused region, after syncthreads)
#define DBH   0
#define DBL   20480
#define DSN   40960
#define DRED  41472          // 16 floats (lp/cm warp partials)
#define DFLAG 41536          // int: last-block flag
#define DSQ   33280

__global__ __launch_bounds__(256, 2) void k_fused(const float* __restrict__ x,
                                                  const float* __restrict__ pb,
                                                  const float* __restrict__ embed,
                                                  float* __restrict__ out,
                                                  int out_size) {
    extern __shared__ char sm[];
    uint32_t sbase = smem_u32(sm);

    int tid  = threadIdx.x;
    int wid  = tid >> 5;
    int lane = tid & 31;
    int g = lane >> 2;
    int q = lane & 3;

    int b  = blockIdx.x >> 4;
    int t0 = (blockIdx.x & 15) * 256;
    const float* xb = x + (size_t)b * CIN * TT + t0;
    int m0 = wid * 32 + g;

    // ================= Phase 1: projection =================
    float acc[2][8][4];
#pragma unroll
    for (int ti = 0; ti < 2; ++ti)
#pragma unroll
        for (int nb = 0; nb < 8; ++nb)
#pragma unroll
            for (int j = 0; j < 4; ++j) acc[ti][nb][j] = 0.f;

    auto stage_p = [&](int cc, int buf) {
        uint32_t xa = sbase + (buf ? PX1 : PX0);
#pragma unroll
        for (int p = 0; p < 8; ++p) {
            int idx = tid + p * 256;
            int c = idx >> 6;
            int f = idx & 63;
            cpa16(xa + (uint32_t)(c * 260 + f * 4) * 4,
                  xb + (size_t)(cc * 32 + c) * TT + f * 4);
        }
        int ch = cc >> 1;
        int hf = cc & 1;
        const uint4* wh = (const uint4*)(g_wfh + ch * 2560 + hf * 16);
        const uint4* wl = (const uint4*)(g_wfl + ch * 2560 + hf * 16);
        uint32_t ha = sbase + (buf ? PWH1 : PWH0);
        uint32_t la = sbase + (buf ? PWL1 : PWL0);
        {
            int e = tid >> 2;
            int part = tid & 3;
            cpa16(ha + (uint32_t)(e * 96 + part * 16), wh + e * 10 + part);
            cpa16(la + (uint32_t)(e * 96 + part * 16), wl + e * 10 + part);
        }
        CPA_COMMIT();
    };

    stage_p(0, 0);

    for (int cc = 0; cc < 16; ++cc) {
        CPA_WAIT0();
        __syncthreads();
        if (cc + 1 < 16) stage_p(cc + 1, (cc + 1) & 1);

        const float* xs = (const float*)(sm + ((cc & 1) ? PX1 : PX0));
        const unsigned char* sWh = (const unsigned char*)(sm + ((cc & 1) ? PWH1 : PWH0));
        const unsigned char* sWl = (const unsigned char*)(sm + ((cc & 1) ? PWL1 : PWL0));

#pragma unroll
        for (int s = 0; s < 2; ++s) {
            int c = s * 16 + 2 * q;
            uint32_t Xh[2][4], Xl[2][4];
#pragma unroll
            for (int ti = 0; ti < 2; ++ti) {
                int m = m0 + ti * 16;
                f16s(make_float2(xs[c * 260 + m],           xs[(c + 1) * 260 + m]),     Xh[ti][0], Xl[ti][0]);
                f16s(make_float2(xs[c * 260 + m + 8],       xs[(c + 1) * 260 + m + 8]), Xh[ti][1], Xl[ti][1]);
                f16s(make_float2(xs[(c + 8) * 260 + m],     xs[(c + 9) * 260 + m]),     Xh[ti][2], Xl[ti][2]);
                f16s(make_float2(xs[(c + 8) * 260 + m + 8], xs[(c + 9) * 260 + m + 8]), Xh[ti][3], Xl[ti][3]);
            }
#pragma unroll
            for (int nb = 0; nb < 8; ++nb) {
                uint32_t boff = (uint32_t)((nb * 8 + g) * 96 + q * 8 + s * 32);
                uint2 bh = *(const uint2*)(sWh + boff);
                uint2 bl = *(const uint2*)(sWl + boff);
#pragma unroll
                for (int ti = 0; ti < 2; ++ti) {
                    MMAF16(acc[ti][nb][0], acc[ti][nb][1], acc[ti][nb][2], acc[ti][nb][3],
                           Xh[ti][0], Xh[ti][1], Xh[ti][2], Xh[ti][3], bh.x, bh.y);
                    MMAF16(acc[ti][nb][0], acc[ti][nb][1], acc[ti][nb][2], acc[ti][nb][3],
                           Xh[ti][0], Xh[ti][1], Xh[ti][2], Xh[ti][3], bl.x, bl.y);
                    MMAF16(acc[ti][nb][0], acc[ti][nb][1], acc[ti][nb][2], acc[ti][nb][3],
                           Xl[ti][0], Xl[ti][1], Xl[ti][2], Xl[ti][3], bh.x, bh.y);
                }
            }
        }
    }

    // ---- bias + ||h||^2 + split accumulators directly into dist A frags ----
    uint32_t A0h[4][4], A0l[4][4], A1h[4][4], A1l[4][4];
    float hn0 = 0.f, hn1 = 0.f, hn2 = 0.f, hn3 = 0.f;
#pragma unroll
    for (int nb = 0; nb < 8; ++nb) {
        float2 bv = *(const float2*)(pb + nb * 8 + 2 * q);
        int s = nb >> 1;
        int odd = nb & 1;
        {   // ti = 0 (rows m0, m0+8)
            float v0 = acc[0][nb][0] + bv.x;
            float v1 = acc[0][nb][1] + bv.y;
            float v2 = acc[0][nb][2] + bv.x;
            float v3 = acc[0][nb][3] + bv.y;
            hn0 += v0 * v0 + v1 * v1;
            hn1 += v2 * v2 + v3 * v3;
            f16s(make_float2(v0, v1), A0h[s][odd ? 2 : 0], A0l[s][odd ? 2 : 0]);
            f16s(make_float2(v2, v3), A0h[s][odd ? 3 : 1], A0l[s][odd ? 3 : 1]);
        }
        {   // ti = 1 (rows m0+16, m0+24)
            float v0 = acc[1][nb][0] + bv.x;
            float v1 = acc[1][nb][1] + bv.y;
            float v2 = acc[1][nb][2] + bv.x;
            float v3 = acc[1][nb][3] + bv.y;
            hn2 += v0 * v0 + v1 * v1;
            hn3 += v2 * v2 + v3 * v3;
            f16s(make_float2(v0, v1), A1h[s][odd ? 2 : 0], A1l[s][odd ? 2 : 0]);
            f16s(make_float2(v2, v3), A1h[s][odd ? 3 : 1], A1l[s][odd ? 3 : 1]);
        }
    }

    __syncthreads();   // projection smem fully dead before dist overlay

    // ================= Phase 2: distance argmin =================
    uint32_t a_sbh = sbase + DBH;
    uint32_t a_sbl = sbase + DBL;
    uint32_t a_sn  = sbase + DSN;
    float* red = (float*)(sm + DRED);

    auto stage = [&](int c, int buf) {
        const uint4* gh = ((const uint4*)g_ebh) + c * 640;
        const uint4* gl = ((const uint4*)g_ebl) + c * 640;
#pragma unroll
        for (int p = 0; p < 3; ++p) {
            int i = tid + p * 256;
            if (i < 640) {
                cpa16(a_sbh + buf * 10240 + i * 16, gh + i);
                cpa16(a_sbl + buf * 10240 + i * 16, gl + i);
            }
        }
        if (tid < 16)
            cpa16(a_sn + buf * 256 + tid * 16,
                  ((const uint4*)(g_enorm + c * 64)) + tid);
        CPA_COMMIT();
    };

    float bA0 = 3.4e38f, bB0 = 3.4e38f, bA1 = 3.4e38f, bB1 = 3.4e38f;
    int   kA0 = 0, kB0 = 0, kA1 = 0, kB1 = 0;

    stage(0, 0);

    for (int c = 0; c < 32; ++c) {
        CPA_WAIT0();
        __syncthreads();
        if (c + 1 < 32) stage(c + 1, (c + 1) & 1);

        const unsigned char* bufh = (const unsigned char*)(sm + DBH + (c & 1) * 10240);
        const unsigned char* bufl = (const unsigned char*)(sm + DBL + (c & 1) * 10240);
        const float* sn = (const float*)(sm + DSN + (c & 1) * 256);

#pragma unroll
        for (int nb = 0; nb < 8; ++nb) {
            float c0 = 0.f, c1 = 0.f, c2 = 0.f, c3 = 0.f;
            float d0 = 0.f, d1 = 0.f, d2 = 0.f, d3 = 0.f;
            uint32_t bo = (uint32_t)((nb * 8 + g) * 160 + q * 8);
#pragma unroll
            for (int s = 0; s < 4; ++s) {
                uint2 bh = *(const uint2*)(bufh + bo + s * 32);
                uint2 bl = *(const uint2*)(bufl + bo + s * 32);
                MMAF16(c0, c1, c2, c3, A0h[s][0], A0h[s][1], A0h[s][2], A0h[s][3], bh.x, bh.y);
                MMAF16(d0, d1, d2, d3, A1h[s][0], A1h[s][1], A1h[s][2], A1h[s][3], bh.x, bh.y);
                MMAF16(c0, c1, c2, c3, A0h[s][0], A0h[s][1], A0h[s][2], A0h[s][3], bl.x, bl.y);
                MMAF16(d0, d1, d2, d3, A1h[s][0], A1h[s][1], A1h[s][2], A1h[s][3], bl.x, bl.y);
                MMAF16(c0, c1, c2, c3, A0l[s][0], A0l[s][1], A0l[s][2], A0l[s][3], bh.x, bh.y);
                MMAF16(d0, d1, d2, d3, A1l[s][0], A1l[s][1], A1l[s][2], A1l[s][3], bh.x, bh.y);
            }
            int kb = c * 64 + nb * 8;
            float sn0 = sn[nb * 8 + 2 * q];
            float sn1 = sn[nb * 8 + 2 * q + 1];
            float s0 = fmaf(-2.f, c0, sn0);
            float s1 = fmaf(-2.f, c1, sn1);
            float s2 = fmaf(-2.f, c2, sn0);
            float s3 = fmaf(-2.f, c3, sn1);
            float u0 = fmaf(-2.f, d0, sn0);
            float u1 = fmaf(-2.f, d1, sn1);
            float u2 = fmaf(-2.f, d2, sn0);
            float u3 = fmaf(-2.f, d3, sn1);
            if (s0 < bA0) { bA0 = s0; kA0 = kb + 2 * q; }
            if (s1 < bA0) { bA0 = s1; kA0 = kb + 2 * q + 1; }
            if (s2 < bB0) { bB0 = s2; kB0 = kb + 2 * q; }
            if (s3 < bB0) { bB0 = s3; kB0 = kb + 2 * q + 1; }
            if (u0 < bA1) { bA1 = u0; kA1 = kb + 2 * q; }
            if (u1 < bA1) { bA1 = u1; kA1 = kb + 2 * q + 1; }
            if (u2 < bB1) { bB1 = u2; kB1 = kb + 2 * q; }
            if (u3 < bB1) { bB1 = u3; kB1 = kb + 2 * q + 1; }
        }
    }

#pragma unroll
    for (int off = 1; off <= 2; off <<= 1) {
        float o; int k;
        o = __shfl_xor_sync(0xffffffffu, bA0, off);
        k = __shfl_xor_sync(0xffffffffu, kA0, off);
        if (o < bA0 || (o == bA0 && k < kA0)) { bA0 = o; kA0 = k; }
        o = __shfl_xor_sync(0xffffffffu, bB0, off);
        k = __shfl_xor_sync(0xffffffffu, kB0, off);
        if (o < bB0 || (o == bB0 && k < kB0)) { bB0 = o; kB0 = k; }
        o = __shfl_xor_sync(0xffffffffu, bA1, off);
        k = __shfl_xor_sync(0xffffffffu, kA1, off);
        if (o < bA1 || (o == bA1 && k < kA1)) { bA1 = o; kA1 = k; }
        o = __shfl_xor_sync(0xffffffffu, bB1, off);
        k = __shfl_xor_sync(0xffffffffu, kB1, off);
        if (o < bB1 || (o == bB1 && k < kB1)) { bB1 = o; kB1 = k; }
        hn0 += __shfl_xor_sync(0xffffffffu, hn0, off);
        hn1 += __shfl_xor_sync(0xffffffffu, hn1, off);
        hn2 += __shfl_xor_sync(0xffffffffu, hn2, off);
        hn3 += __shfl_xor_sync(0xffffffffu, hn3, off);
    }

    __syncthreads();   // all fragment-buffer reads complete before overlay

    int* sq = (int*)(sm + DSQ);     // 256 point indices
    if (q == 0) {
        sq[wid * 32 + g]      = kA0;
        sq[wid * 32 + 8 + g]  = kB0;
        sq[wid * 32 + 16 + g] = kA1;
        sq[wid * 32 + 24 + g] = kB1;
        atomicAdd(&g_counts[kA0], 1);
        atomicAdd(&g_counts[kB0], 1);
        atomicAdd(&g_counts[kA1], 1);
        atomicAdd(&g_counts[kB1], 1);
    }

    float contrib = (q == 0)
        ? (bA0 + hn0) + (bB0 + hn1) + (bA1 + hn2) + (bB1 + hn3) : 0.f;
#pragma unroll
    for (int off = 16; off > 0; off >>= 1)
        contrib += __shfl_xor_sync(0xffffffffu, contrib, off);
    if (lane == 0) red[wid] = contrib;
    __syncthreads();

    int* flag = (int*)(sm + DFLAG);
    if (tid == 0) {
        float s = 0.f;
#pragma unroll
        for (int i = 0; i < 8; ++i) s += red[i];
        g_partials[blockIdx.x] = s;
        __threadfence();
        int prev = atomicAdd(&g_done, 1);
        *flag = (prev == 255) ? 1 : 0;
    }

    // ---- gather + transpose + output, 2 passes of 128 t ----
    float* zq = (float*)sm;          // [128][65]
    for (int p = 0; p < 2; ++p) {
        __syncthreads();
        int tl = tid >> 1;
        int hf = tid & 1;
        int qi = sq[p * 128 + tl];
        const float4* ep = (const float4*)(embed + (size_t)qi * EE + hf * 32);
#pragma unroll
        for (int j = 0; j < 8; ++j) {
            float4 z = ep[j];
            int e = hf * 32 + j * 4;
            zq[tl * 65 + e + 0] = z.x;
            zq[tl * 65 + e + 1] = z.y;
            zq[tl * 65 + e + 2] = z.z;
            zq[tl * 65 + e + 3] = z.w;
        }
        __syncthreads();
#pragma unroll
        for (int i = 0; i < 32; ++i) {
            int idx = i * 256 + tid;
            int e  = idx >> 7;
            int tt = idx & 127;
            out[((size_t)(b * EE + e)) * TT + t0 + p * 128 + tt] =
                zq[tt * 65 + e];
        }
    }

    // ---- last CTA: finalize scalars (counts/partials all committed) ----
    __syncthreads();
    if (*flag) {
        __threadfence();
        float lp = 0.f;
#pragma unroll
        for (int k = tid; k < KK; k += 256) {
            float pp = (float)g_counts[k] * (1.f / (float)NPTS);
            lp -= pp * logf(pp + 1e-10f);
        }
        float cm = g_partials[tid];
#pragma unroll
        for (int o = 16; o > 0; o >>= 1) {
            lp += __shfl_xor_sync(0xffffffffu, lp, o);
            cm += __shfl_xor_sync(0xffffffffu, cm, o);
        }
        float* slp = (float*)(sm + DRED);        // 8 floats
        float* scm = (float*)(sm + DRED + 32);   // 8 floats
        if (lane == 0) { slp[wid] = lp; scm[wid] = cm; }
        __syncthreads();
        if (out_size >= ZLEN + 18) {
            if (tid == 0) {
                float tl = 0.f, tc = 0.f;
#pragma unroll
                for (int i = 0; i < 8; ++i) { tl += slp[i]; tc += scm[i]; }
                out[ZLEN + 17] = tl;
                out[ZLEN] = 0.25f * tc / ((float)NPTS * (float)EE);
            }
            if (tid >= 64 && tid < 80)
                out[ZLEN + 1 + (tid - 64)] = (float)(log(2048.0) * 4096.0);
        }
    }
}

// ---------------- launch ----------------
extern "C" void kernel_launch(void* const* d_in, const int* in_sizes, int n_in,
                              void* d_out, int out_size) {
    const float* x  = (const float*)d_in[0];   // [B, CIN, T]
    const float* w  = (const float*)d_in[1];   // [E, CIN]
    const float* pb = (const float*)d_in[2];   // [E]
    const float* em = (const float*)d_in[3];   // [K, E]
    float* out = (float*)d_out;

    static int smem_set = 0;
    if (!smem_set) {
        cudaFuncSetAttribute(k_fused,
                             cudaFuncAttributeMaxDynamicSharedMemorySize, PTOT);
        smem_set = 1;
    }

    k_prep<<<256, 256>>>(em, w);
    k_fused<<<NPTS / 256, 256, PTOT>>>(x, pb, em, out, out_size);
}